// round 1
// baseline (speedup 1.0000x reference)
#include <cuda_runtime.h>
#include <cstdint>

// Problem dims
#define BB   16384
#define DOBS 512
#define NE   8
#define NA   32
#define G1   256
#define G2   128
#define E1   1024
#define E2   512
#define E3   256
#define NP   (2*BB)   // total (token, expert) pairs = 32768

// ---------------- scratch (static device allocations) ----------------
__device__ float g_g1[BB*G1];
__device__ float g_g2[BB*G2];
__device__ int   g_tidx[BB*2];
__device__ float g_tw[BB*2];
__device__ int   g_counts[NE];
__device__ int   g_off[NE+1];
__device__ int   g_tile128[NE+1];
__device__ int   g_tile32[NE+1];
__device__ int   g_cursor[NE];
__device__ int   g_tok[NP];
__device__ float g_wt[NP];
__device__ float g_h1[(size_t)NP*E1];
__device__ float g_h2[(size_t)NP*E2];
__device__ float g_h3[(size_t)NP*E3];

__device__ __forceinline__ float eluf(float x) { return x > 0.f ? x : expm1f(x); }

// ---------------- init: zero counters ----------------
__global__ void init_kernel() {
    int t = threadIdx.x;
    if (t < NE) { g_counts[t] = 0; g_cursor[t] = 0; }
}

// ---------------- tiled SGEMM: C = act(A @ W + bias) ----------------
// BM=BN=128, BK=8, 256 threads, 8x8 per-thread microtile.
// GROUPED: rows are partitioned per-expert via g_off/g_tile128, W/bias per expert.
// GATHER:  A row index comes from g_tok[] (layer-1 reads obs rows).
template<bool GROUPED, bool GATHER, bool ELU>
__global__ __launch_bounds__(256)
void sgemm_kernel(const float* __restrict__ A, const float* __restrict__ W,
                  const float* __restrict__ bias, float* __restrict__ C,
                  int M, int K, int N)
{
    int row0, rowEnd;
    if (GROUPED) {
        int bx = blockIdx.x;
        if (bx >= g_tile128[NE]) return;
        int e = 0;
        while (bx >= g_tile128[e+1]) e++;
        row0   = g_off[e] + (bx - g_tile128[e]) * 128;
        rowEnd = g_off[e+1];
        if (row0 >= rowEnd) return;
        W    += (size_t)e * K * N;
        bias += e * N;
    } else {
        row0   = blockIdx.x * 128;
        rowEnd = M;
    }
    const int n0 = blockIdx.y * 128;

    __shared__ float As[8][128];
    __shared__ float Bs[8][128];

    const int tid  = threadIdx.x;
    const int aRow = tid >> 1, aCol = (tid & 1) * 4;
    const int bRow = tid >> 5, bCol = (tid & 31) * 4;
    const int tx   = tid & 15, ty   = tid >> 4;

    float acc[8][8];
#pragma unroll
    for (int i = 0; i < 8; i++)
#pragma unroll
        for (int j = 0; j < 8; j++) acc[i][j] = 0.f;

    const int grow = row0 + aRow;
    const bool avalid = grow < rowEnd;
    const float* arow_ptr = nullptr;
    if (avalid) {
        if (GATHER) arow_ptr = A + (size_t)g_tok[grow] * K;
        else        arow_ptr = A + (size_t)grow * K;
    }

    for (int k0 = 0; k0 < K; k0 += 8) {
        float4 av = make_float4(0.f, 0.f, 0.f, 0.f);
        if (avalid) av = *(const float4*)(arow_ptr + k0 + aCol);
        float4 bv = *(const float4*)(W + (size_t)(k0 + bRow) * N + n0 + bCol);
        __syncthreads();
        As[aCol+0][aRow] = av.x; As[aCol+1][aRow] = av.y;
        As[aCol+2][aRow] = av.z; As[aCol+3][aRow] = av.w;
        *(float4*)&Bs[bRow][bCol] = bv;
        __syncthreads();
#pragma unroll
        for (int kk = 0; kk < 8; kk++) {
            float4 a0 = *(float4*)&As[kk][ty*8];
            float4 a1 = *(float4*)&As[kk][ty*8+4];
            float4 b0 = *(float4*)&Bs[kk][tx*8];
            float4 b1 = *(float4*)&Bs[kk][tx*8+4];
            float a[8] = {a0.x,a0.y,a0.z,a0.w,a1.x,a1.y,a1.z,a1.w};
            float b[8] = {b0.x,b0.y,b0.z,b0.w,b1.x,b1.y,b1.z,b1.w};
#pragma unroll
            for (int i = 0; i < 8; i++)
#pragma unroll
                for (int j = 0; j < 8; j++) acc[i][j] += a[i]*b[j];
        }
    }

#pragma unroll
    for (int i = 0; i < 8; i++) {
        int r = row0 + ty*8 + i;
        if (r < rowEnd) {
#pragma unroll
            for (int j = 0; j < 8; j++) {
                int c = n0 + tx*8 + j;
                float v = acc[i][j] + bias[c];
                if (ELU) v = eluf(v);
                C[(size_t)r * N + c] = v;
            }
        }
    }
}

// ---------------- gating head: logits + top-2 + renorm + counts ----------------
// 64 tokens per block, 128 threads.
__global__ __launch_bounds__(128)
void gate_topk_kernel(const float* __restrict__ gw3, const float* __restrict__ gb3)
{
    __shared__ float sG[64*129];
    __shared__ float sW[G2*NE];
    __shared__ float sB[NE];
    const int tid = threadIdx.x;
    const int b0  = blockIdx.x * 64;
    for (int i = tid; i < 64*G2; i += 128)
        sG[(i >> 7)*129 + (i & 127)] = g_g2[(size_t)b0*G2 + i];
    for (int i = tid; i < G2*NE; i += 128) sW[i] = gw3[i];
    if (tid < NE) sB[tid] = gb3[tid];
    __syncthreads();
    if (tid < 64) {
        float lg[NE];
#pragma unroll
        for (int j = 0; j < NE; j++) lg[j] = sB[j];
        for (int k = 0; k < G2; k++) {
            float gv = sG[tid*129 + k];
#pragma unroll
            for (int j = 0; j < NE; j++) lg[j] += gv * sW[k*NE + j];
        }
        // top-2 (ties -> lower index, matching lax.top_k)
        int i0 = 0; float m0 = lg[0];
#pragma unroll
        for (int j = 1; j < NE; j++) if (lg[j] > m0) { m0 = lg[j]; i0 = j; }
        int i1 = -1; float m1 = -3.4e38f;
#pragma unroll
        for (int j = 0; j < NE; j++) if (j != i0 && lg[j] > m1) { m1 = lg[j]; i1 = j; }
        float e1  = expf(m1 - m0);
        float inv = 1.f / (1.f + e1);
        int b = b0 + tid;
        g_tidx[b*2+0] = i0; g_tidx[b*2+1] = i1;
        g_tw[b*2+0] = inv;  g_tw[b*2+1] = e1 * inv;
        atomicAdd(&g_counts[i0], 1);
        atomicAdd(&g_counts[i1], 1);
    }
}

// ---------------- prefix sums: pair offsets + tile offsets ----------------
__global__ void offsets_kernel()
{
    if (threadIdx.x == 0 && blockIdx.x == 0) {
        int o = 0, t128 = 0, t32 = 0;
        for (int e = 0; e < NE; e++) {
            g_off[e] = o; g_tile128[e] = t128; g_tile32[e] = t32;
            int c = g_counts[e];
            o += c; t128 += (c + 127) >> 7; t32 += (c + 31) >> 5;
        }
        g_off[NE] = o; g_tile128[NE] = t128; g_tile32[NE] = t32;
    }
}

// ---------------- scatter tokens into per-expert slot lists ----------------
__global__ __launch_bounds__(256)
void scatter_kernel()
{
    const int b    = blockIdx.x * 256 + threadIdx.x;
    const int lane = threadIdx.x & 31;
#pragma unroll
    for (int s = 0; s < 2; s++) {
        int   e = g_tidx[b*2 + s];
        float w = g_tw[b*2 + s];
#pragma unroll
        for (int ee = 0; ee < NE; ee++) {
            unsigned m = __ballot_sync(0xffffffffu, e == ee);
            if (e == ee) {
                int rank   = __popc(m & ((1u << lane) - 1u));
                int leader = __ffs(m) - 1;
                int base = 0;
                if (lane == leader) base = atomicAdd(&g_cursor[ee], __popc(m));
                base = __shfl_sync(m, base, leader);
                int p = g_off[ee] + base + rank;
                g_tok[p] = b; g_wt[p] = w;
            }
        }
    }
}

// ---------------- layer 4 (K=256, N=32) fused with weighted combine ----------------
// 32 rows per block, 256 threads: thread = (row, 4 cols).
__global__ __launch_bounds__(256)
void l4_combine_kernel(const float* __restrict__ H3, const float* __restrict__ W4,
                       const float* __restrict__ B4, float* __restrict__ out)
{
    const int bx = blockIdx.x;
    if (bx >= g_tile32[NE]) return;
    int e = 0;
    while (bx >= g_tile32[e+1]) e++;
    const int row0   = g_off[e] + (bx - g_tile32[e]) * 32;
    const int rowEnd = g_off[e+1];

    __shared__ float sW[E3*NA];   // 32 KB
    const float* We = W4 + (size_t)e * E3 * NA;
    for (int i = threadIdx.x; i < E3*NA/4; i += 256)
        *(float4*)&sW[i*4] = *(const float4*)&We[i*4];
    __syncthreads();

    const int r  = threadIdx.x >> 3;
    const int c4 = (threadIdx.x & 7) * 4;
    const int row = row0 + r;
    if (row >= rowEnd) return;

    const float* h = H3 + (size_t)row * E3;
    float a0 = 0.f, a1 = 0.f, a2 = 0.f, a3 = 0.f;
#pragma unroll 4
    for (int k = 0; k < E3; k += 4) {
        float4 hv = *(const float4*)&h[k];
        float4 w0 = *(float4*)&sW[(k+0)*NA + c4];
        float4 w1 = *(float4*)&sW[(k+1)*NA + c4];
        float4 w2 = *(float4*)&sW[(k+2)*NA + c4];
        float4 w3 = *(float4*)&sW[(k+3)*NA + c4];
        a0 += hv.x*w0.x + hv.y*w1.x + hv.z*w2.x + hv.w*w3.x;
        a1 += hv.x*w0.y + hv.y*w1.y + hv.z*w2.y + hv.w*w3.y;
        a2 += hv.x*w0.z + hv.y*w1.z + hv.z*w2.z + hv.w*w3.z;
        a3 += hv.x*w0.w + hv.y*w1.w + hv.z*w2.w + hv.w*w3.w;
    }
    const int   tok = g_tok[row];
    const float w   = g_wt[row];
    float* o = out + (size_t)tok * NA + c4;
    atomicAdd(o+0, w*(a0 + B4[e*NA + c4 + 0]));
    atomicAdd(o+1, w*(a1 + B4[e*NA + c4 + 1]));
    atomicAdd(o+2, w*(a2 + B4[e*NA + c4 + 2]));
    atomicAdd(o+3, w*(a3 + B4[e*NA + c4 + 3]));
}

// ---------------- launch ----------------
extern "C" void kernel_launch(void* const* d_in, const int* in_sizes, int n_in,
                              void* d_out, int out_size)
{
    const float* obs = (const float*)d_in[0];
    const float* gw1 = (const float*)d_in[1];
    const float* gb1 = (const float*)d_in[2];
    const float* gw2 = (const float*)d_in[3];
    const float* gb2 = (const float*)d_in[4];
    const float* gw3 = (const float*)d_in[5];
    const float* gb3 = (const float*)d_in[6];
    const float* ew1 = (const float*)d_in[7];
    const float* eb1 = (const float*)d_in[8];
    const float* ew2 = (const float*)d_in[9];
    const float* eb2 = (const float*)d_in[10];
    const float* ew3 = (const float*)d_in[11];
    const float* eb3 = (const float*)d_in[12];
    const float* ew4 = (const float*)d_in[13];
    const float* eb4 = (const float*)d_in[14];
    float* out = (float*)d_out;

    float *pg1, *pg2, *ph1, *ph2, *ph3;
    cudaGetSymbolAddress((void**)&pg1, g_g1);
    cudaGetSymbolAddress((void**)&pg2, g_g2);
    cudaGetSymbolAddress((void**)&ph1, g_h1);
    cudaGetSymbolAddress((void**)&ph2, g_h2);
    cudaGetSymbolAddress((void**)&ph3, g_h3);

    init_kernel<<<1, 32>>>();
    cudaMemsetAsync(out, 0, (size_t)out_size * sizeof(float));

    // gating MLP
    sgemm_kernel<false,false,true><<<dim3(BB/128, G1/128), 256>>>(obs, gw1, gb1, pg1, BB, DOBS, G1);
    sgemm_kernel<false,false,true><<<dim3(BB/128, G2/128), 256>>>(pg1, gw2, gb2, pg2, BB, G1, G2);
    gate_topk_kernel<<<BB/64, 128>>>(gw3, gb3);
    offsets_kernel<<<1, 32>>>();
    scatter_kernel<<<BB/256, 256>>>();

    // grouped expert layers (upper-bound grids; extra blocks exit early)
    const int T128 = NP/128 + NE;   // 264
    const int T32  = NP/32  + NE;   // 1032
    sgemm_kernel<true,true ,true><<<dim3(T128, E1/128), 256>>>(obs, ew1, eb1, ph1, 0, DOBS, E1);
    sgemm_kernel<true,false,true><<<dim3(T128, E2/128), 256>>>(ph1, ew2, eb2, ph2, 0, E1, E2);
    sgemm_kernel<true,false,true><<<dim3(T128, E3/128), 256>>>(ph2, ew3, eb3, ph3, 0, E2, E3);

    // layer 4 + weighted combine (2 commutative atomic adds per output -> deterministic)
    l4_combine_kernel<<<T32, 256>>>(ph3, ew4, eb4, out);
}